// round 15
// baseline (speedup 1.0000x reference)
#include <cuda_runtime.h>
#include <cstdint>

#define BB 512
#define TT 2000
#define HH 50
#define CH 32
#define HSTRIDE 68                      // floats per hist row, rows 16B aligned
#define HIST_FLOATS (33 * HSTRIDE)      // 2244 floats per warp slot
#define XS_FLOATS (2 * 96)              // double-buffered x per warp slot
#define NW 8                            // warps per CTA (each owns one batch)
#define DSM_BYTES ((NW * HIST_FLOATS + NW * XS_FLOATS) * 4)   // 77,952 B

typedef unsigned long long ull;

__device__ __forceinline__ ull packf2(float a, float b) {
    ull r;
    asm("mov.b64 %0, {%1, %2};" : "=l"(r) : "f"(a), "f"(b));
    return r;
}
__device__ __forceinline__ void unpackf2(ull v, float& lo, float& hi) {
    asm("mov.b64 {%0, %1}, %2;" : "=f"(lo), "=f"(hi) : "l"(v));
}
#define FMA2(acc, a, b) \
    asm("fma.rn.f32x2 %0, %1, %2, %0;" : "+l"(acc) : "l"(a), "l"(b))
#define ADD2(dst, a, b) \
    asm("add.rn.f32x2 %0, %1, %2;" : "=l"(dst) : "l"(a), "l"(b))
#define CP_ASYNC16(dst_u32, src) \
    asm volatile("cp.async.ca.shared.global [%0], [%1], 16;" :: "r"(dst_u32), "l"(src))
#define CP_COMMIT() asm volatile("cp.async.commit_group;")
#define CP_WAIT0()  asm volatile("cp.async.wait_group 0;")

__global__ __launch_bounds__(32 * NW, 1)
void rnn_kernel(const float* __restrict__ x,
                const float* __restrict__ W_ih,
                const float* __restrict__ W_hh,
                const float* __restrict__ b_ih,
                const float* __restrict__ b_hh,
                const float* __restrict__ W_out,
                const float* __restrict__ b_out,
                float* __restrict__ y)
{
    extern __shared__ __align__(16) float dsm[];
    __shared__ ull  wosh[3][25];
    __shared__ float bosh[3];

    const int tid  = threadIdx.x;
    const int warp = tid >> 5;
    const int lane = tid & 31;
    const int b = blockIdx.x * NW + warp;     // one batch per warp

    if (tid < 75) {
        const int d = tid / 25, q = tid % 25;
        wosh[d][q] = packf2(W_out[d * HH + 2 * q], W_out[d * HH + 2 * q + 1]);
    }
    if (tid < 3) bosh[tid] = b_out[tid];

    const int j0 = lane;            // < 50 always
    const int j1 = lane + 32;       // real only for lanes 0..17
    const bool j1v = (j1 < HH);

    // per-lane packed W_hh rows (25 k-pairs each); zero rows for padded j1
    ull w0[25], w1[25];
#pragma unroll
    for (int q = 0; q < 25; q++) {
        w0[q] = packf2(W_hh[j0 * HH + 2 * q], W_hh[j0 * HH + 2 * q + 1]);
        w1[q] = j1v ? packf2(W_hh[j1 * HH + 2 * q], W_hh[j1 * HH + 2 * q + 1]) : 0ull;
    }
    const float wi0a = W_ih[j0 * 3 + 0], wi0b = W_ih[j0 * 3 + 1], wi0c = W_ih[j0 * 3 + 2];
    const float bias0 = b_ih[j0] + b_hh[j0];
    const float wi1a = j1v ? W_ih[j1 * 3 + 0] : 0.f;
    const float wi1b = j1v ? W_ih[j1 * 3 + 1] : 0.f;
    const float wi1c = j1v ? W_ih[j1 * 3 + 2] : 0.f;
    const float bias1 = j1v ? (b_ih[j1] + b_hh[j1]) : 0.f;

    float* const hwarp = dsm + warp * HIST_FLOATS;
    float* const xwarp = dsm + NW * HIST_FLOATS + warp * XS_FLOATS;
    hwarp[lane] = 0.f;           // h_{-1} = 0 (cols 50..63 rewritten as 0 each step)
    hwarp[lane + 32] = 0.f;

    const float* __restrict__ xb = x + (size_t)b * TT * 3;
    float* __restrict__ yb = y + (size_t)b * TT * 3;

    // stage x chunk 0 via cp.async (96 floats = lanes 0..23 x 16B)
    const uint32_t xs_base0 = (uint32_t)__cvta_generic_to_shared(xwarp);
    const uint32_t xs_base1 = xs_base0 + 96 * 4;
    if (lane < 24) CP_ASYNC16(xs_base0 + lane * 16, xb + lane * 4);
    CP_COMMIT();
    CP_WAIT0();
    __syncthreads();     // wosh/bosh + x chunk 0 visibility (outside hot loop)

    int buf = 0;
    for (int base = 0; base < TT; base += CH) {
        const int cnt = min(CH, TT - base);     // 32 or 16, both %4 == 0

        // prefetch next chunk's x straight into the other smem buffer
        {
            const int ncnt = min(CH, TT - base - CH);
            if (base + CH < TT && lane * 16 < ncnt * 12) {
                const uint32_t dst = (buf ? xs_base0 : xs_base1) + lane * 16;
                CP_ASYNC16(dst, xb + (size_t)(base + CH) * 3 + lane * 4);
            }
            CP_COMMIT();
        }

        const float* __restrict__ xp = xwarp + buf * 96;

        // ---- recurrence: warp-private smem, no syncs ----
        for (int g = 0; g < cnt; g += 4) {
#pragma unroll
            for (int u = 0; u < 4; u++) {
                const int s = g + u;
                const float x0 = xp[3 * s + 0];
                const float x1 = xp[3 * s + 1];
                const float x2 = xp[3 * s + 2];
                const float xh0 = fmaf(x2, wi0c, fmaf(x1, wi0b, fmaf(x0, wi0a, bias0)));
                const float xh1 = fmaf(x2, wi1c, fmaf(x1, wi1b, fmaf(x0, wi1a, bias1)));

                const float* hr = hwarp + s * HSTRIDE;
                ull a0 = packf2(xh0, 0.f), a1 = 0ull;
                ull b0 = packf2(xh1, 0.f), b1 = 0ull;
#pragma unroll
                for (int p = 0; p < 12; p++) {
                    const ulonglong2 hv = *reinterpret_cast<const ulonglong2*>(hr + 4 * p);
                    FMA2(a0, hv.x, w0[2 * p]);
                    FMA2(b0, hv.x, w1[2 * p]);
                    FMA2(a1, hv.y, w0[2 * p + 1]);
                    FMA2(b1, hv.y, w1[2 * p + 1]);
                }
                const ull hl = *reinterpret_cast<const ull*>(hr + 48);  // h[48..49]
                FMA2(a0, hl, w0[24]);
                FMA2(b0, hl, w1[24]);

                ull s0, s1;
                ADD2(s0, a0, a1);
                ADD2(s1, b0, b1);
                float l0, u0, l1, u1;
                unpackf2(s0, l0, u0);
                unpackf2(s1, l1, u1);
                const float h0 = fmaxf(l0 + u0, 0.f);
                const float h1 = fmaxf(l1 + u1, 0.f);   // exactly 0 for padded j1

                float* hw = hwarp + (s + 1) * HSTRIDE;
                hw[lane] = h0;
                hw[lane + 32] = h1;
            }
        }

        // carry h_{last} into row 0 for next chunk (same-warp in-order smem)
        hwarp[lane] = hwarp[cnt * HSTRIDE + lane];
        hwarp[lane + 32] = hwarp[cnt * HSTRIDE + lane + 32];

        // ---- chunk projection: lane s owns timestep base+s (row s+1) ----
        if (lane < cnt) {
            const float* pr = hwarp + (lane + 1) * HSTRIDE;
            ull a0 = 0ull, c0 = 0ull, a1 = 0ull, c1 = 0ull, a2 = 0ull, c2 = 0ull;
#pragma unroll
            for (int p = 0; p < 12; p++) {
                const ulonglong2 hv = *reinterpret_cast<const ulonglong2*>(pr + 4 * p);
                FMA2(a0, hv.x, wosh[0][2 * p]); FMA2(c0, hv.y, wosh[0][2 * p + 1]);
                FMA2(a1, hv.x, wosh[1][2 * p]); FMA2(c1, hv.y, wosh[1][2 * p + 1]);
                FMA2(a2, hv.x, wosh[2][2 * p]); FMA2(c2, hv.y, wosh[2][2 * p + 1]);
            }
            const ull hl = *reinterpret_cast<const ull*>(pr + 48);
            FMA2(a0, hl, wosh[0][24]);
            FMA2(a1, hl, wosh[1][24]);
            FMA2(a2, hl, wosh[2][24]);

            ull s0, s1, s2;
            ADD2(s0, a0, c0); ADD2(s1, a1, c1); ADD2(s2, a2, c2);
            float p0l, p0h, p1l, p1h, p2l, p2h;
            unpackf2(s0, p0l, p0h);
            unpackf2(s1, p1l, p1h);
            unpackf2(s2, p2l, p2h);
            float* yo = yb + (size_t)(base + lane) * 3;
            yo[0] = p0l + p0h + bosh[0];
            yo[1] = p1l + p1h + bosh[1];
            yo[2] = p2l + p2h + bosh[2];
        }

        // next chunk's x must be in smem and warp-visible
        CP_WAIT0();
        __syncwarp();
        buf ^= 1;
    }
}

extern "C" void kernel_launch(void* const* d_in, const int* in_sizes, int n_in,
                              void* d_out, int out_size) {
    const float* x     = (const float*)d_in[0];
    const float* W_ih  = (const float*)d_in[1];
    const float* W_hh  = (const float*)d_in[2];
    const float* b_ih  = (const float*)d_in[3];
    const float* b_hh  = (const float*)d_in[4];
    const float* W_out = (const float*)d_in[5];
    const float* b_out = (const float*)d_in[6];
    float* y = (float*)d_out;

    cudaFuncSetAttribute(rnn_kernel, cudaFuncAttributeMaxDynamicSharedMemorySize,
                         DSM_BYTES);
    rnn_kernel<<<BB / NW, 32 * NW, DSM_BYTES>>>(x, W_ih, W_hh, b_ih, b_hh,
                                                W_out, b_out, y);
}

// round 16
// speedup vs baseline: 1.4105x; 1.4105x over previous
#include <cuda_runtime.h>
#include <cstdint>

#define BB 512
#define TT 2000
#define HH 50
#define CH 32
#define HSTRIDE 68     // floats per hist row, 16B-aligned rows

typedef unsigned long long ull;

__device__ __forceinline__ ull packf2(float a, float b) {
    ull r;
    asm("mov.b64 %0, {%1, %2};" : "=l"(r) : "f"(a), "f"(b));
    return r;
}
__device__ __forceinline__ void unpackf2(ull v, float& lo, float& hi) {
    asm("mov.b64 {%0, %1}, %2;" : "=f"(lo), "=f"(hi) : "l"(v));
}
#define FMA2(acc, a, b) \
    asm("fma.rn.f32x2 %0, %1, %2, %0;" : "+l"(acc) : "l"(a), "l"(b))
#define ADD2(dst, a, b) \
    asm("add.rn.f32x2 %0, %1, %2;" : "=l"(dst) : "l"(a), "l"(b))
#define CP_ASYNC4(dst_u32, src) \
    asm volatile("cp.async.ca.shared.global [%0], [%1], 4;" :: "r"(dst_u32), "l"(src))
#define CP_COMMIT() asm volatile("cp.async.commit_group;")
#define CP_WAIT0()  asm volatile("cp.async.wait_group 0;")

__global__ __launch_bounds__(128, 1)
void rnn_kernel(const float* __restrict__ x,
                const float* __restrict__ W_ih,
                const float* __restrict__ W_hh,
                const float* __restrict__ b_ih,
                const float* __restrict__ b_hh,
                const float* __restrict__ W_out,
                const float* __restrict__ b_out,
                float* __restrict__ y)
{
    // per-warp 33-row history: step s reads row s, writes row s+1; NO syncs.
    __shared__ __align__(16) float hist[4][CH + 1][HSTRIDE];   // 35,904 B
    // x staged DUPLICATED: per step 8 floats (x0,x0,x1,x1,x2,x2,pad,pad)
    __shared__ __align__(16) float xs[4][2][CH][8];            //  8,192 B
    __shared__ ull  wosh[3][25];
    __shared__ float bosh[3];

    const int tid  = threadIdx.x;
    const int warp = tid >> 5;
    const int lane = tid & 31;
    const int b = blockIdx.x * 4 + warp;

    if (tid < 75) {
        const int d = tid / 25, q = tid % 25;
        wosh[d][q] = packf2(W_out[d * HH + 2 * q], W_out[d * HH + 2 * q + 1]);
    }
    if (tid < 3) bosh[tid] = b_out[tid];

    const int j0 = lane;            // < 50 always
    const int j1 = lane + 32;       // real only for lanes 0..17
    const bool j1v = (j1 < HH);

    // per-lane packed W_hh rows (25 k-pairs each); zero rows for padded j1
    ull w0[25], w1[25];
#pragma unroll
    for (int q = 0; q < 25; q++) {
        w0[q] = packf2(W_hh[j0 * HH + 2 * q], W_hh[j0 * HH + 2 * q + 1]);
        w1[q] = j1v ? packf2(W_hh[j1 * HH + 2 * q], W_hh[j1 * HH + 2 * q + 1]) : 0ull;
    }
    // packed input-projection weights: (j0 part, j1 part)
    const ull WIA = packf2(W_ih[j0 * 3 + 0], j1v ? W_ih[j1 * 3 + 0] : 0.f);
    const ull WIB = packf2(W_ih[j0 * 3 + 1], j1v ? W_ih[j1 * 3 + 1] : 0.f);
    const ull WIC = packf2(W_ih[j0 * 3 + 2], j1v ? W_ih[j1 * 3 + 2] : 0.f);
    const ull BIAS01 = packf2(b_ih[j0] + b_hh[j0],
                              j1v ? (b_ih[j1] + b_hh[j1]) : 0.f);

    float* const hwarp = &hist[warp][0][0];
    hwarp[lane] = 0.f;           // h_{-1} = 0 (cols 50..63 rewritten as 0 each step)
    hwarp[lane + 32] = 0.f;

    const float* __restrict__ xb = x + (size_t)b * TT * 3;
    float* __restrict__ yb = y + (size_t)b * TT * 3;

    // stage x chunk 0: duplicated scatter  x[t][c] -> slot t*32 + c*8 {+0,+4}
    const uint32_t xs_base0 = (uint32_t)__cvta_generic_to_shared(&xs[warp][0][0][0]);
    const uint32_t xs_base1 = (uint32_t)__cvta_generic_to_shared(&xs[warp][1][0][0]);
#pragma unroll
    for (int e = 0; e < 3; e++) {
        const int gi = lane + e * 32;                 // 0..95
        const uint32_t doff = (uint32_t)((gi / 3) * 32 + (gi % 3) * 8);
        CP_ASYNC4(xs_base0 + doff, xb + gi);
        CP_ASYNC4(xs_base0 + doff + 4, xb + gi);
    }
    CP_COMMIT();
    CP_WAIT0();
    __syncthreads();     // wosh/bosh + x chunk 0 visibility (outside hot loop)

    int buf = 0;
    for (int base = 0; base < TT; base += CH) {
        const int cnt = min(CH, TT - base);     // 32 or 16, both %4 == 0

        // prefetch next chunk's x straight into the other smem buffer
        {
            const int ncnt = min(CH, TT - base - CH);
            if (base + CH < TT) {
                const uint32_t dbase = (buf ? xs_base0 : xs_base1);
#pragma unroll
                for (int e = 0; e < 3; e++) {
                    const int gi = lane + e * 32;
                    if (gi < ncnt * 3) {
                        const uint32_t doff = (uint32_t)((gi / 3) * 32 + (gi % 3) * 8);
                        CP_ASYNC4(dbase + doff, xb + (size_t)(base + CH) * 3 + gi);
                        CP_ASYNC4(dbase + doff + 4, xb + (size_t)(base + CH) * 3 + gi);
                    }
                }
            }
            CP_COMMIT();
        }

        const float* __restrict__ xp = &xs[warp][buf][0][0];

        // ---- recurrence: warp-private smem, no syncs ----
        for (int g = 0; g < cnt; g += 4) {
#pragma unroll
            for (int u = 0; u < 4; u++) {
                const int s = g + u;
                // x duplicated: (x0,x0),(x1,x1),(x2,x2)
                const ulonglong2 xd = *reinterpret_cast<const ulonglong2*>(xp + s * 8);
                const ull X2 = *reinterpret_cast<const ull*>(xp + s * 8 + 4);
                // packed xh: T = (xh0, xh1) in 3 FMA2
                ull T = BIAS01;
                FMA2(T, xd.x, WIA);
                FMA2(T, xd.y, WIB);
                FMA2(T, X2, WIC);
                float xh0, xh1;
                unpackf2(T, xh0, xh1);

                const float* hr = hwarp + s * HSTRIDE;
                ull a0 = packf2(xh0, 0.f), a1 = 0ull;
                ull b0 = packf2(xh1, 0.f), b1 = 0ull;
#pragma unroll
                for (int p = 0; p < 12; p++) {
                    const ulonglong2 hv = *reinterpret_cast<const ulonglong2*>(hr + 4 * p);
                    FMA2(a0, hv.x, w0[2 * p]);
                    FMA2(b0, hv.x, w1[2 * p]);
                    FMA2(a1, hv.y, w0[2 * p + 1]);
                    FMA2(b1, hv.y, w1[2 * p + 1]);
                }
                const ull hl = *reinterpret_cast<const ull*>(hr + 48);  // h[48..49]
                FMA2(a0, hl, w0[24]);
                FMA2(b0, hl, w1[24]);

                // tail: one packed horizontal combine instead of 2 FADD
                ull s0, s1;
                ADD2(s0, a0, a1);
                ADD2(s1, b0, b1);
                float A, B2, C, D;
                unpackf2(s0, A, B2);
                unpackf2(s1, C, D);
                const ull P = packf2(A, C);
                const ull Q = packf2(B2, D);
                ull R;
                ADD2(R, P, Q);
                float r0, r1;
                unpackf2(R, r0, r1);
                const float h0 = fmaxf(r0, 0.f);
                const float h1 = fmaxf(r1, 0.f);   // exactly 0 for padded j1

                float* hw = hwarp + (s + 1) * HSTRIDE;
                hw[lane] = h0;
                hw[lane + 32] = h1;
            }
        }

        // carry h_{last} into row 0 for next chunk (same-warp in-order smem)
        hwarp[lane] = hwarp[cnt * HSTRIDE + lane];
        hwarp[lane + 32] = hwarp[cnt * HSTRIDE + lane + 32];

        // ---- chunk projection: lane s owns timestep base+s (row s+1) ----
        if (lane < cnt) {
            const float* pr = hwarp + (lane + 1) * HSTRIDE;
            ull a0 = 0ull, c0 = 0ull, a1 = 0ull, c1 = 0ull, a2 = 0ull, c2 = 0ull;
#pragma unroll
            for (int p = 0; p < 12; p++) {
                const ulonglong2 hv = *reinterpret_cast<const ulonglong2*>(pr + 4 * p);
                FMA2(a0, hv.x, wosh[0][2 * p]); FMA2(c0, hv.y, wosh[0][2 * p + 1]);
                FMA2(a1, hv.x, wosh[1][2 * p]); FMA2(c1, hv.y, wosh[1][2 * p + 1]);
                FMA2(a2, hv.x, wosh[2][2 * p]); FMA2(c2, hv.y, wosh[2][2 * p + 1]);
            }
            const ull hl = *reinterpret_cast<const ull*>(pr + 48);
            FMA2(a0, hl, wosh[0][24]);
            FMA2(a1, hl, wosh[1][24]);
            FMA2(a2, hl, wosh[2][24]);

            ull s0, s1, s2;
            ADD2(s0, a0, c0); ADD2(s1, a1, c1); ADD2(s2, a2, c2);
            float p0l, p0h, p1l, p1h, p2l, p2h;
            unpackf2(s0, p0l, p0h);
            unpackf2(s1, p1l, p1h);
            unpackf2(s2, p2l, p2h);
            float* yo = yb + (size_t)(base + lane) * 3;
            yo[0] = p0l + p0h + bosh[0];
            yo[1] = p1l + p1h + bosh[1];
            yo[2] = p2l + p2h + bosh[2];
        }

        // next chunk's x must be in smem and warp-visible
        CP_WAIT0();
        __syncwarp();
        buf ^= 1;
    }
}

extern "C" void kernel_launch(void* const* d_in, const int* in_sizes, int n_in,
                              void* d_out, int out_size) {
    const float* x     = (const float*)d_in[0];
    const float* W_ih  = (const float*)d_in[1];
    const float* W_hh  = (const float*)d_in[2];
    const float* b_ih  = (const float*)d_in[3];
    const float* b_hh  = (const float*)d_in[4];
    const float* W_out = (const float*)d_in[5];
    const float* b_out = (const float*)d_in[6];
    float* y = (float*)d_out;

    rnn_kernel<<<BB / 4, 128>>>(x, W_ih, W_hh, b_ih, b_hh, W_out, b_out, y);
}

// round 17
// speedup vs baseline: 1.7268x; 1.2242x over previous
#include <cuda_runtime.h>
#include <cstdint>

#define BB 512
#define TT 2000
#define HH 50
#define CH 32
#define HSTRIDE 68     // floats per hist row, 16B-aligned rows (272B)
#define XBUF_FLOATS ((CH + 1) * 4)    // 132 floats per x buffer (pad slot at CH)

typedef unsigned long long ull;

__device__ __forceinline__ ull packf2(float a, float b) {
    ull r;
    asm("mov.b64 %0, {%1, %2};" : "=l"(r) : "f"(a), "f"(b));
    return r;
}
__device__ __forceinline__ void unpackf2(ull v, float& lo, float& hi) {
    asm("mov.b64 {%0, %1}, %2;" : "=f"(lo), "=f"(hi) : "l"(v));
}
#define FMA2(acc, a, b) \
    asm("fma.rn.f32x2 %0, %1, %2, %0;" : "+l"(acc) : "l"(a), "l"(b))
#define ADD2(dst, a, b) \
    asm("add.rn.f32x2 %0, %1, %2;" : "=l"(dst) : "l"(a), "l"(b))
#define CP_ASYNC4(dst_u32, src) \
    asm volatile("cp.async.ca.shared.global [%0], [%1], 4;" :: "r"(dst_u32), "l"(src))
#define CP_COMMIT() asm volatile("cp.async.commit_group;")
#define CP_WAIT0()  asm volatile("cp.async.wait_group 0;")

__global__ __launch_bounds__(128, 1)
void rnn_kernel(const float* __restrict__ x,
                const float* __restrict__ W_ih,
                const float* __restrict__ W_hh,
                const float* __restrict__ b_ih,
                const float* __restrict__ b_hh,
                const float* __restrict__ W_out,
                const float* __restrict__ b_out,
                float* __restrict__ y)
{
    // per-warp 33-row history: step s reads row s, writes row s+1; NO syncs.
    __shared__ __align__(16) float hist[4][CH + 1][HSTRIDE];   // 35,904 B
    // x staged [CH+1][4] per buffer: slot t = (x0,x1,x2,pad); slot CH = pad
    __shared__ __align__(16) float xs[4][2][XBUF_FLOATS];      //  4,224 B
    __shared__ ull  wosh[3][25];
    __shared__ float bosh[3];

    const int tid  = threadIdx.x;
    const int warp = tid >> 5;
    const int lane = tid & 31;
    const int b = blockIdx.x * 4 + warp;

    if (tid < 75) {
        const int d = tid / 25, q = tid % 25;
        wosh[d][q] = packf2(W_out[d * HH + 2 * q], W_out[d * HH + 2 * q + 1]);
    }
    if (tid < 3) bosh[tid] = b_out[tid];

    // adjacent-j partition: lane owns j0 = 2*lane, j1 = 2*lane+1 (lanes 0..24)
    const int j0 = 2 * lane;
    const int j1 = 2 * lane + 1;
    const bool act = (lane < 25);

    // per-lane packed W_hh rows (25 k-pairs each); zero rows for inactive lanes
    ull w0[25], w1[25];
#pragma unroll
    for (int q = 0; q < 25; q++) {
        w0[q] = act ? packf2(W_hh[j0 * HH + 2 * q], W_hh[j0 * HH + 2 * q + 1]) : 0ull;
        w1[q] = act ? packf2(W_hh[j1 * HH + 2 * q], W_hh[j1 * HH + 2 * q + 1]) : 0ull;
    }
    const float wi0a = act ? W_ih[j0 * 3 + 0] : 0.f;
    const float wi0b = act ? W_ih[j0 * 3 + 1] : 0.f;
    const float wi0c = act ? W_ih[j0 * 3 + 2] : 0.f;
    const float bias0 = act ? (b_ih[j0] + b_hh[j0]) : 0.f;
    const float wi1a = act ? W_ih[j1 * 3 + 0] : 0.f;
    const float wi1b = act ? W_ih[j1 * 3 + 1] : 0.f;
    const float wi1c = act ? W_ih[j1 * 3 + 2] : 0.f;
    const float bias1 = act ? (b_ih[j1] + b_hh[j1]) : 0.f;

    float* const hwarp = &hist[warp][0][0];
    hwarp[lane] = 0.f;           // h_{-1} = 0 (row pad 200..255B rewritten each step)
    hwarp[lane + 32] = 0.f;

    const float* __restrict__ xb = x + (size_t)b * TT * 3;
    float* __restrict__ yb = y + (size_t)b * TT * 3;

    // stage x chunk 0: scatter x[t][c] -> buffer slot t*16 + c*4
    const uint32_t xs_base0 = (uint32_t)__cvta_generic_to_shared(&xs[warp][0][0]);
    const uint32_t xs_base1 = (uint32_t)__cvta_generic_to_shared(&xs[warp][1][0]);
#pragma unroll
    for (int e = 0; e < 3; e++) {
        const int gi = lane + e * 32;                 // 0..95
        const uint32_t doff = (uint32_t)((gi / 3) * 16 + (gi % 3) * 4);
        CP_ASYNC4(xs_base0 + doff, xb + gi);
    }
    CP_COMMIT();
    CP_WAIT0();
    __syncthreads();     // wosh/bosh + x chunk 0 visibility (outside hot loop)

    int buf = 0;
    for (int base = 0; base < TT; base += CH) {
        const int cnt = min(CH, TT - base);     // 32 or 16, both %4 == 0

        // prefetch next chunk's x into the other smem buffer (scatter layout)
        if (base + CH < TT) {
            const int ncnt = min(CH, TT - base - CH);
            const uint32_t dbase = buf ? xs_base0 : xs_base1;
#pragma unroll
            for (int e = 0; e < 3; e++) {
                const int gi = lane + e * 32;
                if (gi < ncnt * 3) {
                    const uint32_t doff = (uint32_t)((gi / 3) * 16 + (gi % 3) * 4);
                    CP_ASYNC4(dbase + doff, xb + (size_t)(base + CH) * 3 + gi);
                }
            }
        }
        CP_COMMIT();

        const float* __restrict__ xp = &xs[warp][buf][0];

        // xh for step 0 of this chunk (pipeline prologue)
        float xh0c, xh1c;
        {
            const float4 xv = *reinterpret_cast<const float4*>(xp);
            xh0c = fmaf(xv.z, wi0c, fmaf(xv.y, wi0b, fmaf(xv.x, wi0a, bias0)));
            xh1c = fmaf(xv.z, wi1c, fmaf(xv.y, wi1b, fmaf(xv.x, wi1a, bias1)));
        }

        // ---- recurrence: warp-private smem, no syncs, xh pipelined ----
        for (int g = 0; g < cnt; g += 4) {
#pragma unroll
            for (int u = 0; u < 4; u++) {
                const int s = g + u;
                const float* hr = hwarp + s * HSTRIDE;
                // accumulators seeded with this step's (pre-computed) xh
                ull a0 = packf2(xh0c, 0.f), a1 = 0ull;
                ull b0 = packf2(xh1c, 0.f), b1 = 0ull;
#pragma unroll
                for (int p = 0; p < 12; p++) {
                    const ulonglong2 hv = *reinterpret_cast<const ulonglong2*>(hr + 4 * p);
                    FMA2(a0, hv.x, w0[2 * p]);
                    FMA2(b0, hv.x, w1[2 * p]);
                    FMA2(a1, hv.y, w0[2 * p + 1]);
                    FMA2(b1, hv.y, w1[2 * p + 1]);
                }
                const ull hl = *reinterpret_cast<const ull*>(hr + 48);  // h[48..49]
                FMA2(a0, hl, w0[24]);
                FMA2(b0, hl, w1[24]);

                // pipeline: compute next step's xh while FMAs drain
                {
                    const float4 xv = *reinterpret_cast<const float4*>(xp + (s + 1) * 4);
                    xh0c = fmaf(xv.z, wi0c, fmaf(xv.y, wi0b, fmaf(xv.x, wi0a, bias0)));
                    xh1c = fmaf(xv.z, wi1c, fmaf(xv.y, wi1b, fmaf(xv.x, wi1a, bias1)));
                }

                ull s0, s1;
                ADD2(s0, a0, a1);
                ADD2(s1, b0, b1);
                float l0, u0, l1, u1;
                unpackf2(s0, l0, u0);
                unpackf2(s1, l1, u1);
                const float h0 = fmaxf(l0 + u0, 0.f);
                const float h1 = fmaxf(l1 + u1, 0.f);   // 0 for inactive lanes

                // single STS.64: (h[2*lane], h[2*lane+1]); lanes 25..31 write row pad
                float* hw = hwarp + (s + 1) * HSTRIDE;
                *reinterpret_cast<ull*>(hw + lane * 2) = packf2(h0, h1);
            }
        }

        // carry h_{last} (row cnt) into row 0 (same-warp in-order smem)
        *reinterpret_cast<ull*>(hwarp + lane * 2) =
            *reinterpret_cast<const ull*>(hwarp + cnt * HSTRIDE + lane * 2);

        // ---- chunk projection: lane s owns timestep base+s (row s+1) ----
        if (lane < cnt) {
            const float* pr = hwarp + (lane + 1) * HSTRIDE;
            ull a0 = 0ull, c0 = 0ull, a1 = 0ull, c1 = 0ull, a2 = 0ull, c2 = 0ull;
#pragma unroll
            for (int p = 0; p < 12; p++) {
                const ulonglong2 hv = *reinterpret_cast<const ulonglong2*>(pr + 4 * p);
                FMA2(a0, hv.x, wosh[0][2 * p]); FMA2(c0, hv.y, wosh[0][2 * p + 1]);
                FMA2(a1, hv.x, wosh[1][2 * p]); FMA2(c1, hv.y, wosh[1][2 * p + 1]);
                FMA2(a2, hv.x, wosh[2][2 * p]); FMA2(c2, hv.y, wosh[2][2 * p + 1]);
            }
            const ull hl = *reinterpret_cast<const ull*>(pr + 48);
            FMA2(a0, hl, wosh[0][24]);
            FMA2(a1, hl, wosh[1][24]);
            FMA2(a2, hl, wosh[2][24]);

            ull s0, s1, s2;
            ADD2(s0, a0, c0); ADD2(s1, a1, c1); ADD2(s2, a2, c2);
            float p0l, p0h, p1l, p1h, p2l, p2h;
            unpackf2(s0, p0l, p0h);
            unpackf2(s1, p1l, p1h);
            unpackf2(s2, p2l, p2h);
            float* yo = yb + (size_t)(base + lane) * 3;
            yo[0] = p0l + p0h + bosh[0];
            yo[1] = p1l + p1h + bosh[1];
            yo[2] = p2l + p2h + bosh[2];
        }

        // next chunk's x must be in smem and warp-visible
        CP_WAIT0();
        __syncwarp();
        buf ^= 1;
    }
}

extern "C" void kernel_launch(void* const* d_in, const int* in_sizes, int n_in,
                              void* d_out, int out_size) {
    const float* x     = (const float*)d_in[0];
    const float* W_ih  = (const float*)d_in[1];
    const float* W_hh  = (const float*)d_in[2];
    const float* b_ih  = (const float*)d_in[3];
    const float* b_hh  = (const float*)d_in[4];
    const float* W_out = (const float*)d_in[5];
    const float* b_out = (const float*)d_in[6];
    float* y = (float*)d_out;

    rnn_kernel<<<BB / 4, 128>>>(x, W_ih, W_hh, b_ih, b_hh, W_out, b_out, y);
}